// round 7
// baseline (speedup 1.0000x reference)
#include <cuda_runtime.h>
#include <cuda_bf16.h>

// Sbert idf-weighted masked mean pooling — persistent CTAs + weight prefetch.
// hidden [B, L, D] f32, ids [B, L] i32, mask [B, L] i32, idf [V] f32
// out[b, d] = sum_l hidden[b,l,d] * (mask[b,l] ? idf[ids[b,l]] : 0) / max(sum_l mask[b,l], 1e-9)

constexpr int L  = 100;
constexpr int D  = 768;
constexpr int D4 = D / 4;          // 192 float4 lanes per row
constexpr int THREADS = D4;        // one float4 column group per thread
constexpr int GRID_MAX = 1520;     // 152 SMs x 10 CTAs (6 warps each -> 60/64 warps)

__global__ __launch_bounds__(THREADS) void sbert_pool_kernel(
    const float* __restrict__ hidden,
    const int*   __restrict__ ids,
    const int*   __restrict__ mask,
    const float* __restrict__ idf,
    float*       __restrict__ out,
    int B)
{
    // Triple-buffered per-token weights. Single barrier per iteration is safe:
    // iter i phase-B reads w[buf]; the earliest later write to w[buf] is in
    // iter i+2, which every thread reaches only after iter i+1's barrier —
    // by which point all iter-i reads have retired (program order).
    __shared__ float w[3][L];

    const int t = threadIdx.x;
    int b = blockIdx.x;

    // Prologue: weights + mask count for this CTA's first row
    int m = 0;
    if (b < B && t < L) {
        const int base = b * L + t;
        m = mask[base];
        w[0][t] = m ? idf[ids[base]] : 0.0f;
    }
    int cnt = __syncthreads_count(m != 0);
    float inv = 1.0f / fmaxf((float)cnt, 1e-9f);
    int buf = 0;

    for (; b < B; b += gridDim.x) {
        // ── Prefetch weights for the NEXT row (hides the mask->ids->idf
        //    dependent-gather latency under this row's streaming phase) ──
        const int b_next = b + gridDim.x;
        const int nbuf = (buf == 2) ? 0 : buf + 1;
        int mn = 0;
        if (b_next < B && t < L) {
            const int base = b_next * L + t;
            mn = mask[base];
            w[nbuf][t] = mn ? idf[ids[base]] : 0.0f;
        }
        const int cnt_next = __syncthreads_count(mn != 0);

        // ── Stream current row: 100 x 3072 B, evict-first (single-use) ──
        const float4* __restrict__ hp =
            reinterpret_cast<const float4*>(hidden + (size_t)b * L * D) + t;

        float4 acc = make_float4(0.f, 0.f, 0.f, 0.f);
        #pragma unroll 5
        for (int l = 0; l < L; ++l) {
            const float4 h = __ldcs(hp + (size_t)l * D4);
            const float wv = w[buf][l];
            acc.x = fmaf(h.x, wv, acc.x);
            acc.y = fmaf(h.y, wv, acc.y);
            acc.z = fmaf(h.z, wv, acc.z);
            acc.w = fmaf(h.w, wv, acc.w);
        }

        acc.x *= inv; acc.y *= inv; acc.z *= inv; acc.w *= inv;
        __stcs(reinterpret_cast<float4*>(out + (size_t)b * D) + t, acc);

        inv = 1.0f / fmaxf((float)cnt_next, 1e-9f);
        buf = nbuf;
    }
}

extern "C" void kernel_launch(void* const* d_in, const int* in_sizes, int n_in,
                              void* d_out, int out_size) {
    const float* hidden = (const float*)d_in[0];
    const int*   ids    = (const int*)  d_in[1];
    const int*   mask   = (const int*)  d_in[2];
    const float* idf    = (const float*)d_in[3];
    float*       out    = (float*)d_out;

    const int B = out_size / D;                    // 4096
    const int grid = (B < GRID_MAX) ? B : GRID_MAX;
    sbert_pool_kernel<<<grid, THREADS>>>(hidden, ids, mask, idf, out, B);
}

// round 9
// speedup vs baseline: 1.0022x; 1.0022x over previous
#include <cuda_runtime.h>
#include <cuda_bf16.h>

// Sbert idf-weighted masked mean pooling — R4 structure + streaming cache hints.
// hidden [B, L, D] f32, ids [B, L] i32, mask [B, L] i32, idf [V] f32
// out[b, d] = sum_l hidden[b,l,d] * (mask[b,l] ? idf[ids[b,l]] : 0) / max(sum_l mask[b,l], 1e-9)

constexpr int L = 100;
constexpr int D = 768;
constexpr int D4 = D / 4;        // 192 float4 lanes per row
constexpr int THREADS = D4;      // 192 threads: 1 float4 column group per thread

__global__ __launch_bounds__(THREADS) void sbert_pool_kernel(
    const float* __restrict__ hidden,
    const int*   __restrict__ ids,
    const int*   __restrict__ mask,
    const float* __restrict__ idf,
    float*       __restrict__ out)
{
    __shared__ float w[L];

    const int b = blockIdx.x;
    const int t = threadIdx.x;

    // Phase A: per-token weights into smem; mask count via syncthreads_count.
    // mask/ids are small & multi-referenced per wave -> default (caching) loads;
    // idf table (122 KB) is hot across all CTAs -> default loads keep it in L2.
    int m = 0;
    if (t < L) {
        const int base = b * L + t;
        m = mask[base];
        float wv = 0.0f;
        if (m) wv = idf[ids[base]];
        w[t] = wv;
    }
    const int cnt = __syncthreads_count(m != 0);
    const float inv = 1.0f / fmaxf((float)cnt, 1e-9f);

    // Phase B: stream 100 rows of hidden. Strictly single-use data ->
    // evict-first (.cs) so it doesn't churn L2 against ids/mask/idf.
    const float4* __restrict__ hp =
        reinterpret_cast<const float4*>(hidden + (size_t)b * L * D) + t;

    float4 acc = make_float4(0.f, 0.f, 0.f, 0.f);
    #pragma unroll 5
    for (int l = 0; l < L; ++l) {
        const float4 h = __ldcs(hp + (size_t)l * D4);
        const float wv = w[l];
        acc.x = fmaf(h.x, wv, acc.x);
        acc.y = fmaf(h.y, wv, acc.y);
        acc.z = fmaf(h.z, wv, acc.z);
        acc.w = fmaf(h.w, wv, acc.w);
    }

    acc.x *= inv; acc.y *= inv; acc.z *= inv; acc.w *= inv;
    __stcs(reinterpret_cast<float4*>(out + (size_t)b * D) + t, acc);
}

extern "C" void kernel_launch(void* const* d_in, const int* in_sizes, int n_in,
                              void* d_out, int out_size) {
    const float* hidden = (const float*)d_in[0];
    const int*   ids    = (const int*)  d_in[1];
    const int*   mask   = (const int*)  d_in[2];
    const float* idf    = (const float*)d_in[3];
    float*       out    = (float*)d_out;

    const int B = out_size / D;   // 4096
    sbert_pool_kernel<<<B, THREADS>>>(hidden, ids, mask, idf, out);
}

// round 10
// speedup vs baseline: 1.7676x; 1.7636x over previous
#include <cuda_runtime.h>
#include <cuda_bf16.h>

// Sbert idf-weighted masked mean pooling — zero-weight row skipping.
// hidden [B, L, D] f32, ids [B, L] i32, mask [B, L] i32, idf [V] f32
// out[b,d] = sum_l hidden[b,l,d] * (mask[b,l] ? idf[ids[b,l]] : 0) / max(sum_l mask[b,l], 1e-9)
//
// Key fact: ~50% of tokens have weight exactly 0 (mask==0). fmaf(h, 0, acc) == acc
// bit-exactly for finite h, so those hidden rows need never be loaded. We compact
// the nonzero-weight token indices (order-preserving, deterministic — no atomics)
// and stream only those rows: ~2x less DRAM traffic, bit-identical output.

constexpr int L = 100;
constexpr int D = 768;
constexpr int D4 = D / 4;        // 192 float4 lanes per row
constexpr int THREADS = D4;      // 192 threads: 1 float4 column group per thread

__global__ __launch_bounds__(THREADS) void sbert_pool_kernel(
    const float* __restrict__ hidden,
    const int*   __restrict__ ids,
    const int*   __restrict__ mask,
    const float* __restrict__ idf,
    float*       __restrict__ out)
{
    __shared__ float w[L];       // per-token weight (dense)
    __shared__ float wc[L];      // compacted nonzero weights (ascending l)
    __shared__ int   idx[L];     // compacted token indices

    const int b = blockIdx.x;
    const int t = threadIdx.x;

    // ── Phase A: gather weights; denominator = mask count ──
    int m = 0;
    float wv = 0.0f;
    if (t < L) {
        const int base = b * L + t;
        m = mask[base];
        if (m) wv = idf[ids[base]];
        w[t] = wv;
    }
    const int cnt = __syncthreads_count(m != 0);          // barrier #1 (w visible)
    const float inv = 1.0f / fmaxf((float)cnt, 1e-9f);

    // ── Phase A2: order-preserving compaction of nonzero-weight tokens.
    //    Each owning thread counts its nonzero predecessors -> deterministic
    //    slot, ascending-l order preserved (accumulation order == dense loop).
    if (t < L && wv != 0.0f) {
        int pos = 0;
        #pragma unroll 4
        for (int j = 0; j < t; ++j) pos += (w[j] != 0.0f);
        idx[pos] = t;
        wc[pos]  = wv;
    }
    const int nnz = __syncthreads_count(t < L && wv != 0.0f);  // barrier #2 (idx/wc visible)

    // ── Phase B: stream only the nnz useful rows of hidden ──
    const float4* __restrict__ hp =
        reinterpret_cast<const float4*>(hidden + (size_t)b * L * D) + t;

    float4 acc = make_float4(0.f, 0.f, 0.f, 0.f);
    #pragma unroll 4
    for (int j = 0; j < nnz; ++j) {
        const float4 h = hp[(size_t)idx[j] * D4];
        const float  wj = wc[j];
        acc.x = fmaf(h.x, wj, acc.x);
        acc.y = fmaf(h.y, wj, acc.y);
        acc.z = fmaf(h.z, wj, acc.z);
        acc.w = fmaf(h.w, wj, acc.w);
    }

    acc.x *= inv; acc.y *= inv; acc.z *= inv; acc.w *= inv;
    reinterpret_cast<float4*>(out + (size_t)b * D)[t] = acc;
}

extern "C" void kernel_launch(void* const* d_in, const int* in_sizes, int n_in,
                              void* d_out, int out_size) {
    const float* hidden = (const float*)d_in[0];
    const int*   ids    = (const int*)  d_in[1];
    const int*   mask   = (const int*)  d_in[2];
    const float* idf    = (const float*)d_in[3];
    float*       out    = (float*)d_out;

    const int B = out_size / D;   // 4096
    sbert_pool_kernel<<<B, THREADS>>>(hidden, ids, mask, idf, out);
}